// round 5
// baseline (speedup 1.0000x reference)
#include <cuda_runtime.h>
#include <math.h>

#define T_TOK 512
#define CHUNK 64
#define NCHUNK 8
#define HH 28
#define WW 28
#define CC 4
#define DM 3136
#define DH 512

#define FSEG 16    // fwd/dadh split-K segments (kseg = 196)
#define PSEG 4     // pred split-K segments (kseg = 128)

// ---------------- device scratch ----------------
__device__ __align__(16) float g_nk[T_TOK * DM];
__device__ __align__(16) float g_nv[T_TOK * DM];
__device__ __align__(16) float g_W1[DM * DH];
__device__ __align__(16) float g_W2[DH * DM];
__device__ __align__(16) float g_b1[DH];
__device__ __align__(16) float g_b2[DM];
__device__ __align__(16) float g_H[CHUNK * DH];
__device__ __align__(16) float g_A[CHUNK * DH];
__device__ __align__(16) float g_A2[CHUNK * DH];
__device__ __align__(16) float g_dpred[CHUNK * DM];
__device__ __align__(16) float g_dh[CHUNK * DH];
__device__ __align__(16) float g_G[CHUNK * CHUNK];            // K@K^T
__device__ __align__(16) float g_fpart[FSEG * CHUNK * DH];    // 2 MB  (fwd & dadh partials)
__device__ __align__(16) float g_ppart[PSEG * CHUNK * DM];    // 3.2 MB (pred partials)
__device__ __align__(16) float g_gpart[FSEG * CHUNK * CHUNK]; // kgram partials

// ---------------- math helpers ----------------
__device__ __forceinline__ float gelu_f(float x) {
    const float c = 0.7978845608028654f, a = 0.044715f;
    float u = c * (x + a * x * x * x);
    return 0.5f * x * (1.0f + tanhf(u));
}
__device__ __forceinline__ float dgelu_f(float x) {
    const float c = 0.7978845608028654f, a = 0.044715f;
    float x2 = x * x;
    float u = c * (x + a * x * x2);
    float th = tanhf(u);
    return 0.5f * (1.0f + th) + 0.5f * x * (1.0f - th * th) * c * (1.0f + 3.0f * a * x2);
}

// ---------------- conv3x3 (k & v) + rmsnorm ----------------
__global__ void conv_rms_kernel(const float* __restrict__ x,
                                const float* __restrict__ wk, const float* __restrict__ bk,
                                const float* __restrict__ wv, const float* __restrict__ bv,
                                const float* __restrict__ sk, const float* __restrict__ sv) {
    __shared__ float swk[144], swv[144], sbk[4], sbv[4], ssk[4], ssv[4];
    int tid = threadIdx.x;
    if (tid < 144) { swk[tid] = wk[tid]; swv[tid] = wv[tid]; }
    if (tid < 4) { sbk[tid] = bk[tid]; sbv[tid] = bv[tid]; ssk[tid] = sk[tid]; ssv[tid] = sv[tid]; }
    __syncthreads();
    int idx = blockIdx.x * blockDim.x + tid;
    if (idx >= T_TOK * HH * WW) return;
    int w = idx % WW;
    int h = (idx / WW) % HH;
    int t = idx / (HH * WW);
    float acck[4], accv[4];
#pragma unroll
    for (int o = 0; o < 4; o++) { acck[o] = sbk[o]; accv[o] = sbv[o]; }
    const float* xt = x + t * (CC * HH * WW);
#pragma unroll
    for (int kh = 0; kh < 3; kh++) {
        int hy = h + kh - 1;
        if (hy < 0 || hy >= HH) continue;
#pragma unroll
        for (int kw = 0; kw < 3; kw++) {
            int wx = w + kw - 1;
            if (wx < 0 || wx >= WW) continue;
            int wbase = (kh * 3 + kw) * 16;
#pragma unroll
            for (int ci = 0; ci < 4; ci++) {
                float xv = xt[ci * (HH * WW) + hy * WW + wx];
#pragma unroll
                for (int o = 0; o < 4; o++) {
                    acck[o] += xv * swk[wbase + ci * 4 + o];
                    accv[o] += xv * swv[wbase + ci * 4 + o];
                }
            }
        }
    }
    float msk = 0.f, msv = 0.f;
#pragma unroll
    for (int o = 0; o < 4; o++) { msk += acck[o] * acck[o]; msv += accv[o] * accv[o]; }
    float ik = rsqrtf(msk * 0.25f + 1e-6f);
    float iv = rsqrtf(msv * 0.25f + 1e-6f);
    int base = t * DM + (h * WW + w) * CC;
#pragma unroll
    for (int o = 0; o < 4; o++) {
        g_nk[base + o] = acck[o] * ik * ssk[o];
        g_nv[base + o] = accv[o] * iv * ssv[o];
    }
}

// ---------------- copy initial params ----------------
__global__ void init_kernel(const float* __restrict__ W1, const float* __restrict__ b1,
                            const float* __restrict__ W2, const float* __restrict__ b2) {
    int i = blockIdx.x * blockDim.x + threadIdx.x;
    int stride = gridDim.x * blockDim.x;
    for (int k = i; k < DM * DH; k += stride) { g_W1[k] = W1[k]; g_W2[k] = W2[k]; }
    if (i < DH) g_b1[i] = b1[i];
    if (i < DM) g_b2[i] = b2[i];
}

// ---------------- unified smem-tiled split-K GEMM ----------------
// C_part[seg][64][NTOT tile 64] = sum_{k in seg} A[64, k] * B[k, n]  (or B[n, k] if TRANSB)
// tile: 64m x 64n, kseg = KSTEP*KITER. block 256 thr, thread 4m x 4n.
template<int TRANSB, int KSTEP, int KITER, int NTILES, int NTOT, int LDA, int LDB>
__global__ void __launch_bounds__(256) gemm_tiled(const float* __restrict__ A,
                                                  const float* __restrict__ B,
                                                  float* __restrict__ Cpart) {
    __shared__ float sA[KSTEP][68];
    __shared__ float sB[KSTEP][68];
    int tid = threadIdx.x;
    int nt = blockIdx.x % NTILES;
    int seg = blockIdx.x / NTILES;
    int n0g = nt * 64;
    int m0 = (tid >> 4) * 4;
    int n0 = (tid & 15) * 4;

    float acc[4][4];
#pragma unroll
    for (int i = 0; i < 4; i++)
#pragma unroll
        for (int j = 0; j < 4; j++) acc[i][j] = 0.f;

    int kbase = seg * (KSTEP * KITER);
    for (int it = 0; it < KITER; it++) {
        int k0 = kbase + it * KSTEP;
        // load A tile (64 x KSTEP) transposed into sA[k][m]
        for (int i = tid; i < 64 * KSTEP; i += 256) {
            int m = i / KSTEP;
            int k = i - m * KSTEP;
            sA[k][m] = A[m * LDA + k0 + k];
        }
        // load B tile into sB[k][n]
        if (!TRANSB) {
            for (int i = tid; i < KSTEP * 16; i += 256) {
                int k = i >> 4;
                int n4 = (i & 15) * 4;
                float4 v = *reinterpret_cast<const float4*>(&B[(k0 + k) * LDB + n0g + n4]);
                sB[k][n4] = v.x; sB[k][n4 + 1] = v.y; sB[k][n4 + 2] = v.z; sB[k][n4 + 3] = v.w;
            }
        } else {
            for (int i = tid; i < 64 * KSTEP; i += 256) {
                int n = i / KSTEP;
                int k = i - n * KSTEP;
                sB[k][n] = B[(n0g + n) * LDB + k0 + k];
            }
        }
        __syncthreads();
#pragma unroll
        for (int kk = 0; kk < KSTEP; kk++) {
            float4 a = *reinterpret_cast<const float4*>(&sA[kk][m0]);
            float4 b = *reinterpret_cast<const float4*>(&sB[kk][n0]);
            float av[4] = {a.x, a.y, a.z, a.w};
            float bv[4] = {b.x, b.y, b.z, b.w};
#pragma unroll
            for (int i = 0; i < 4; i++)
#pragma unroll
                for (int j = 0; j < 4; j++) acc[i][j] += av[i] * bv[j];
        }
        __syncthreads();
    }
    float* P = Cpart + seg * (64 * NTOT) + m0 * NTOT + n0g + n0;
#pragma unroll
    for (int i = 0; i < 4; i++)
        *reinterpret_cast<float4*>(P + i * NTOT) = make_float4(acc[i][0], acc[i][1], acc[i][2], acc[i][3]);
}

// ---------------- reduce fwd partials -> H, A ; and G ----------------
__global__ void reduce1G_kernel() {
    int idx = blockIdx.x * 256 + threadIdx.x;   // 144 blocks: 32768 H/A + 4096 G
    if (idx < 32768) {
        float s = g_b1[idx & (DH - 1)];
#pragma unroll
        for (int sg = 0; sg < FSEG; sg++) s += g_fpart[sg * (CHUNK * DH) + idx];
        g_H[idx] = s;
        g_A[idx] = gelu_f(s);
    } else {
        int g = idx - 32768;
        float s = 0.f;
#pragma unroll
        for (int sg = 0; sg < FSEG; sg++) s += g_gpart[sg * (CHUNK * CHUNK) + g];
        g_G[g] = s;
    }
}

// ---------------- reduce pred partials: mode0 -> dpred, mode1 -> out ----------------
__global__ void reduce2_kernel(int c, int mode, float* __restrict__ out) {
    int idx = blockIdx.x * 256 + threadIdx.x;   // 784 blocks
    int d = idx % DM;
    float s = g_b2[d];
#pragma unroll
    for (int sg = 0; sg < PSEG; sg++) s += g_ppart[sg * (CHUNK * DM) + idx];
    if (mode == 0)
        g_dpred[idx] = 2.0f * (s - g_nv[c * (CHUNK * DM) + idx]);
    else
        out[c * (CHUNK * DM) + idx] = s;
}

// ---------------- reduce dadh partials -> dh (with dgelu) ----------------
__global__ void reduceDh_kernel() {
    int idx = blockIdx.x * 256 + threadIdx.x;   // 128 blocks
    float s = 0.f;
#pragma unroll
    for (int sg = 0; sg < FSEG; sg++) s += g_fpart[sg * (CHUNK * DH) + idx];
    g_dh[idx] = s * dgelu_f(g_H[idx]);
}

// ---------------- fused: W2/W1/bias updates + recall activation A2 ----------------
// A [0,50176):       W2[j,d] -= w * sum_m A[m,j]*dpred[m,d]
// B [50176,100352):  W1[k,j] -= w * sum_m K[m,k]*dh[m,j]
// C [100352,104000): biases
// D [104000,136768): H2 = H - w*(G@dh + colsum(dh)), A2 = gelu(H2)
__global__ void update_recall_kernel(int c, float wgt) {
    int f = blockIdx.x * 256 + threadIdx.x;
    if (f < 50176) {
        int d0 = (f % 784) * 4;
        int j0 = (f / 784) * 8;
        float acc[8][4];
#pragma unroll
        for (int i = 0; i < 8; i++) { acc[i][0]=0; acc[i][1]=0; acc[i][2]=0; acc[i][3]=0; }
#pragma unroll 4
        for (int m = 0; m < CHUNK; m++) {
            float4 p = *reinterpret_cast<const float4*>(g_dpred + m * DM + d0);
            const float* Am = g_A + m * DH + j0;
#pragma unroll
            for (int i = 0; i < 8; i++) {
                float a = Am[i];
                acc[i][0] += a * p.x; acc[i][1] += a * p.y;
                acc[i][2] += a * p.z; acc[i][3] += a * p.w;
            }
        }
#pragma unroll
        for (int i = 0; i < 8; i++) {
            float* Wp = g_W2 + (j0 + i) * DM + d0;
            float4 old = *reinterpret_cast<float4*>(Wp);
            old.x -= wgt * acc[i][0]; old.y -= wgt * acc[i][1];
            old.z -= wgt * acc[i][2]; old.w -= wgt * acc[i][3];
            *reinterpret_cast<float4*>(Wp) = old;
        }
    } else if (f < 100352) {
        int g = f - 50176;
        int j0 = (g % 128) * 4;
        int dd0 = (g / 128) * 8;
        const float* K = g_nk + c * (CHUNK * DM);
        float acc[8][4];
#pragma unroll
        for (int i = 0; i < 8; i++) { acc[i][0]=0; acc[i][1]=0; acc[i][2]=0; acc[i][3]=0; }
#pragma unroll 4
        for (int m = 0; m < CHUNK; m++) {
            float4 gg = *reinterpret_cast<const float4*>(g_dh + m * DH + j0);
            const float* Km = K + m * DM + dd0;
#pragma unroll
            for (int i = 0; i < 8; i++) {
                float kv = Km[i];
                acc[i][0] += kv * gg.x; acc[i][1] += kv * gg.y;
                acc[i][2] += kv * gg.z; acc[i][3] += kv * gg.w;
            }
        }
#pragma unroll
        for (int i = 0; i < 8; i++) {
            float* Wp = g_W1 + (dd0 + i) * DH + j0;
            float4 old = *reinterpret_cast<float4*>(Wp);
            old.x -= wgt * acc[i][0]; old.y -= wgt * acc[i][1];
            old.z -= wgt * acc[i][2]; old.w -= wgt * acc[i][3];
            *reinterpret_cast<float4*>(Wp) = old;
        }
    } else if (f < 104000) {
        int i = f - 100352;
        if (i < DH) {
            float s = 0.f;
#pragma unroll 8
            for (int m = 0; m < CHUNK; m++) s += g_dh[m * DH + i];
            g_b1[i] -= wgt * s;
        } else if (i < DH + DM) {
            int d = i - DH;
            float s = 0.f;
#pragma unroll 8
            for (int m = 0; m < CHUNK; m++) s += g_dpred[m * DM + d];
            g_b2[d] -= wgt * s;
        }
    } else if (f < 136768) {
        int e = f - 104000;
        int m = e >> 9;
        int j = e & (DH - 1);
        float s = 0.f, cs = 0.f;
        const float* Gm = g_G + m * CHUNK;
#pragma unroll 8
        for (int mp = 0; mp < CHUNK; mp++) {
            float d = g_dh[mp * DH + j];
            s += Gm[mp] * d;
            cs += d;
        }
        float H2 = g_H[e] - wgt * (s + cs);
        g_A2[e] = gelu_f(H2);
    }
}

// ---------------- launch ----------------
extern "C" void kernel_launch(void* const* d_in, const int* in_sizes, int n_in,
                              void* d_out, int out_size) {
    const float* x   = (const float*)d_in[0];
    const float* ckw = (const float*)d_in[1];
    const float* ckb = (const float*)d_in[2];
    const float* cvw = (const float*)d_in[3];
    const float* cvb = (const float*)d_in[4];
    const float* rsk = (const float*)d_in[5];
    const float* rsv = (const float*)d_in[6];
    const float* W1  = (const float*)d_in[7];
    const float* b1  = (const float*)d_in[8];
    const float* W2  = (const float*)d_in[9];
    const float* b2  = (const float*)d_in[10];
    float* out = (float*)d_out;

    // weights[i] = eta0*alpha^i * alpha^(CHUNK-1)/alpha^i = const
    float wgt = (float)(0.1 * pow(0.9, 63.0));

    conv_rms_kernel<<<(T_TOK * HH * WW + 255) / 256, 256>>>(x, ckw, ckb, cvw, cvb, rsk, rsv);
    init_kernel<<<512, 256>>>(W1, b1, W2, b2);

    for (int c = 0; c < NCHUNK; c++) {
        const float* Kc = g_nk;  // device-symbol arithmetic must happen on device; pass via offsetting below
        (void)Kc;
        float* nk_base;  cudaGetSymbolAddress((void**)&nk_base, g_nk);
        float* dp_base;  cudaGetSymbolAddress((void**)&dp_base, g_dpred);
        float* a_base;   cudaGetSymbolAddress((void**)&a_base, g_A);
        float* a2_base;  cudaGetSymbolAddress((void**)&a2_base, g_A2);
        float* w1_base;  cudaGetSymbolAddress((void**)&w1_base, g_W1);
        float* w2_base;  cudaGetSymbolAddress((void**)&w2_base, g_W2);
        float* fp_base;  cudaGetSymbolAddress((void**)&fp_base, g_fpart);
        float* pp_base;  cudaGetSymbolAddress((void**)&pp_base, g_ppart);
        float* gp_base;  cudaGetSymbolAddress((void**)&gp_base, g_gpart);
        const float* Kc_p = nk_base + c * (CHUNK * DM);

        // fwd: H = K@W1   (M64, N512, K3136; 16 segs of 196 = 7x28)
        gemm_tiled<0, 28, 7, 8, DH, DM, DH><<<8 * FSEG, 256>>>(Kc_p, w1_base, fp_base);
        // kgram: G = K@K^T (N64; transB)
        gemm_tiled<1, 28, 7, 1, CHUNK, DM, DM><<<1 * FSEG, 256>>>(Kc_p, Kc_p, gp_base);
        reduce1G_kernel<<<144, 256>>>();
        // pred: A@W2 (M64, N3136, K512; 4 segs of 128 = 4x32)
        gemm_tiled<0, 32, 4, 49, DM, DH, DM><<<49 * PSEG, 256>>>(a_base, w2_base, pp_base);
        reduce2_kernel<<<784, 256>>>(c, 0, out);
        // dadh: dpred@W2^T (M64, N512, K3136; transB)
        gemm_tiled<1, 28, 7, 8, DH, DM, DM><<<8 * FSEG, 256>>>(dp_base, w2_base, fp_base);
        reduceDh_kernel<<<128, 256>>>();
        // fused update + recall activation
        update_recall_kernel<<<535, 256>>>(c, wgt);
        // recall pred: A2@W2' -> out
        gemm_tiled<0, 32, 4, 49, DM, DH, DM><<<49 * PSEG, 256>>>(a2_base, w2_base, pp_base);
        reduce2_kernel<<<784, 256>>>(c, 1, out);
    }
}